// round 4
// baseline (speedup 1.0000x reference)
#include <cuda_runtime.h>
#include <cuda_bf16.h>
#include <stdint.h>

// Problem constants (GCNPair): N=50000 nodes, E=600000 edges, D=H=128, O=2, P=4096
#define NNODES 50000
#define NEDGES 600000
#define HFEAT  128
#define NPAIR  4096

// ---------------- scratch (device globals; no runtime allocation) ------------
__device__ int   g_cnt[NNODES];
__device__ int   g_bsums[128];
__device__ int   g_off_l[NNODES + 1];
__device__ int   g_off_r[NNODES + 1];
__device__ int   g_cur[NNODES];
__device__ int   g_csr_l[NEDGES];
__device__ int   g_csr_r[NEDGES];
__device__ float g_w_l  [NEDGES];           // precomputed edge weights dinv[d]*dinv[s]
__device__ float g_w_r  [NEDGES];
__device__ float g_dinv_l[NNODES];
__device__ float g_dinv_r[NNODES];
__device__ float g_aggx [NNODES * HFEAT];   // temp: (A_hat X) per branch, reused
__device__ float g_h1_l [NNODES * HFEAT];   // layer-1 output, left
__device__ float g_h1_r [NNODES * HFEAT];   // layer-1 output, right
__device__ float g_agg2_l[NPAIR * HFEAT];
__device__ float g_agg2_r[NPAIR * HFEAT];
__device__ float g_merged[NPAIR * 2 * HFEAT];
__device__ float g_fc1  [NPAIR * HFEAT];

// ---------------- CSR build ----------------
__global__ void k_zero(int* p, int n) {
    int i = blockIdx.x * blockDim.x + threadIdx.x;
    if (i < n) p[i] = 0;
}

__global__ void k_hist(const int* __restrict__ dst, int e, int* __restrict__ cnt) {
    int i = blockIdx.x * blockDim.x + threadIdx.x;
    if (i < e) atomicAdd(&cnt[dst[i]], 1);
}

// 3-phase exclusive scan of cnt[] -> offsets[]; also seeds cursor[] and dinv[]
__global__ void k_scan_reduce(const int* __restrict__ cnt, int n, int* __restrict__ bsums) {
    __shared__ int sh[1024];
    int i = blockIdx.x * 1024 + threadIdx.x;
    sh[threadIdx.x] = (i < n) ? cnt[i] : 0;
    __syncthreads();
    for (int s = 512; s > 0; s >>= 1) {
        if (threadIdx.x < s) sh[threadIdx.x] += sh[threadIdx.x + s];
        __syncthreads();
    }
    if (threadIdx.x == 0) bsums[blockIdx.x] = sh[0];
}

__global__ void k_scan_mid(int* bsums, int nblk, int* offsets, int n) {
    if (threadIdx.x == 0 && blockIdx.x == 0) {
        int run = 0;
        for (int b = 0; b < nblk; b++) { int v = bsums[b]; bsums[b] = run; run += v; }
        offsets[n] = run;
    }
}

__global__ void k_scan_write(const int* __restrict__ cnt, int n,
                             const int* __restrict__ boffs,
                             int* __restrict__ offsets, int* __restrict__ cursor,
                             float* __restrict__ dinv) {
    __shared__ int sh[1024];
    int i = blockIdx.x * 1024 + threadIdx.x;
    int v = (i < n) ? cnt[i] : 0;
    sh[threadIdx.x] = v;
    __syncthreads();
    for (int s = 1; s < 1024; s <<= 1) {
        int t = 0;
        if (threadIdx.x >= (unsigned)s) t = sh[threadIdx.x - s];
        __syncthreads();
        if (threadIdx.x >= (unsigned)s) sh[threadIdx.x] += t;
        __syncthreads();
    }
    if (i < n) {
        int excl = sh[threadIdx.x] - v + boffs[blockIdx.x];
        offsets[i] = excl;
        cursor[i]  = excl;
        dinv[i]    = rsqrtf((float)(v + 1));   // +1 self-loop; deg > 0 always
    }
}

// Fill CSR and precompute per-edge weight dinv[dst]*dinv[src] so the hot
// aggregation loop has NO random scalar gathers (only the row gather).
__global__ void k_csr_fill(const int* __restrict__ src, const int* __restrict__ dst, int e,
                           int* __restrict__ cursor, int* __restrict__ csr_src,
                           const float* __restrict__ dinv, float* __restrict__ csr_w) {
    int i = blockIdx.x * blockDim.x + threadIdx.x;
    if (i < e) {
        int d = dst[i];
        int s = src[i];
        int pos = atomicAdd(&cursor[d], 1);
        csr_src[pos] = s;
        csr_w[pos]   = dinv[d] * dinv[s];
    }
}

// ---------------- aggregation: one warp per dst row, lane = float4 chunk ------
// Edge loop unrolled x8: per the B300 LDG model cyc/LDG ~= lat_L2/MLP_eff, so
// deeper batching of the independent row gathers moves the loop from
// latency-bound toward the LSU/L2 throughput floor.
__device__ __forceinline__ void fma4(float4& acc, float w, const float4& u) {
    acc.x += w * u.x; acc.y += w * u.y; acc.z += w * u.z; acc.w += w * u.w;
}

__device__ __forceinline__ float4 agg_row(const float4* __restrict__ x,
                                          const int* __restrict__ csr,
                                          const float* __restrict__ csr_w,
                                          const float* __restrict__ dinv,
                                          int node, int lane, int e0, int e1) {
    float di = dinv[node];
    float4 v = x[(size_t)node * 32 + lane];
    float s = di * di;                         // self-loop weight
    float4 acc = make_float4(v.x * s, v.y * s, v.z * s, v.w * s);
    int e = e0;
    for (; e + 8 <= e1; e += 8) {
        int   si[8];
        float wi[8];
#pragma unroll
        for (int j = 0; j < 8; j++) { si[j] = csr[e + j]; wi[j] = csr_w[e + j]; }
        float4 u[8];
#pragma unroll
        for (int j = 0; j < 8; j++) u[j] = x[(size_t)si[j] * 32 + lane];
#pragma unroll
        for (int j = 0; j < 8; j++) fma4(acc, wi[j], u[j]);
    }
    for (; e + 4 <= e1; e += 4) {
        int s0 = csr[e], s1 = csr[e + 1], s2 = csr[e + 2], s3 = csr[e + 3];
        float w0 = csr_w[e],     w1 = csr_w[e + 1];
        float w2 = csr_w[e + 2], w3 = csr_w[e + 3];
        float4 u0 = x[(size_t)s0 * 32 + lane];
        float4 u1 = x[(size_t)s1 * 32 + lane];
        float4 u2 = x[(size_t)s2 * 32 + lane];
        float4 u3 = x[(size_t)s3 * 32 + lane];
        fma4(acc, w0, u0); fma4(acc, w1, u1);
        fma4(acc, w2, u2); fma4(acc, w3, u3);
    }
    for (; e < e1; e++) {
        fma4(acc, csr_w[e], x[(size_t)csr[e] * 32 + lane]);
    }
    return acc;
}

__global__ void k_agg_full(const float4* __restrict__ x,
                           const int* __restrict__ off, const int* __restrict__ csr,
                           const float* __restrict__ csr_w,
                           const float* __restrict__ dinv,
                           float4* __restrict__ out, int n) {
    int w = (blockIdx.x * blockDim.x + threadIdx.x) >> 5;
    int lane = threadIdx.x & 31;
    if (w >= n) return;
    out[(size_t)w * 32 + lane] = agg_row(x, csr, csr_w, dinv, w, lane, off[w], off[w + 1]);
}

// selective aggregation: rows are labels[p*3+col]; only P rows computed
__global__ void k_agg_sel(const float4* __restrict__ h,
                          const int* __restrict__ off, const int* __restrict__ csr,
                          const float* __restrict__ csr_w,
                          const float* __restrict__ dinv,
                          const int* __restrict__ labels, int col,
                          float4* __restrict__ out, int p) {
    int w = (blockIdx.x * blockDim.x + threadIdx.x) >> 5;
    int lane = threadIdx.x & 31;
    if (w >= p) return;
    int node = labels[w * 3 + col];
    out[(size_t)w * 32 + lane] = agg_row(h, csr, csr_w, dinv, node, lane, off[node], off[node + 1]);
}

// ---------------- SGEMM: C[M x 128] = A[M x K] * B[K x 128] (+bias, opt relu) --
// BM=128, BN=128, BK=8, 256 threads, 8x8 per thread. lda == K, ldb == 128.
__global__ __launch_bounds__(256)
void sgemm128(const float* __restrict__ A, const float* __restrict__ B,
              const float* __restrict__ bias, float* __restrict__ C,
              int M, int K, int ldc, int relu) {
    __shared__ float As[8][132];   // padded: conflict-free transposed stores
    __shared__ float Bs[8][128];
    int tid = threadIdx.x;
    int blockRow = blockIdx.x * 128;
    int tr = tid / 16, tc = tid % 16;

    float acc[8][8];
#pragma unroll
    for (int m = 0; m < 8; m++)
#pragma unroll
        for (int nn = 0; nn < 8; nn++) acc[m][nn] = 0.f;

    int aRow  = tid >> 1;          // 0..127
    int aCol4 = (tid & 1) * 4;     // 0 or 4
    int bRow  = tid >> 5;          // 0..7
    int bCol4 = (tid & 31) * 4;

    for (int k0 = 0; k0 < K; k0 += 8) {
        int gr = blockRow + aRow;
        float4 av = (gr < M) ? *(const float4*)(A + (size_t)gr * K + k0 + aCol4)
                             : make_float4(0.f, 0.f, 0.f, 0.f);
        As[aCol4 + 0][aRow] = av.x;
        As[aCol4 + 1][aRow] = av.y;
        As[aCol4 + 2][aRow] = av.z;
        As[aCol4 + 3][aRow] = av.w;
        *(float4*)&Bs[bRow][bCol4] = *(const float4*)(B + (size_t)(k0 + bRow) * 128 + bCol4);
        __syncthreads();
#pragma unroll
        for (int k = 0; k < 8; k++) {
            float4 a0 = *(const float4*)&As[k][tr * 8];
            float4 a1 = *(const float4*)&As[k][tr * 8 + 4];
            float4 b0 = *(const float4*)&Bs[k][tc * 8];
            float4 b1 = *(const float4*)&Bs[k][tc * 8 + 4];
            float ra[8] = {a0.x, a0.y, a0.z, a0.w, a1.x, a1.y, a1.z, a1.w};
            float rb[8] = {b0.x, b0.y, b0.z, b0.w, b1.x, b1.y, b1.z, b1.w};
#pragma unroll
            for (int m = 0; m < 8; m++)
#pragma unroll
                for (int nn = 0; nn < 8; nn++) acc[m][nn] += ra[m] * rb[nn];
        }
        __syncthreads();
    }

#pragma unroll
    for (int m = 0; m < 8; m++) {
        int gr = blockRow + tr * 8 + m;
        if (gr < M) {
#pragma unroll
            for (int nn = 0; nn < 8; nn++) {
                int gc = tc * 8 + nn;
                float v = acc[m][nn] + bias[gc];
                if (relu) v = fmaxf(v, 0.f);
                C[(size_t)gr * ldc + gc] = v;
            }
        }
    }
}

// ---------------- fc2: [P,128] x [128,2] + b, one warp per row ----------------
__global__ void k_fc2(const float4* __restrict__ h, const float* __restrict__ W,
                      const float* __restrict__ b, float* __restrict__ out, int p) {
    int w = (blockIdx.x * blockDim.x + threadIdx.x) >> 5;
    int lane = threadIdx.x & 31;
    if (w >= p) return;
    float4 v = h[(size_t)w * 32 + lane];
    int k = lane * 4;
    float s0 = v.x * W[(k + 0) * 2] + v.y * W[(k + 1) * 2] + v.z * W[(k + 2) * 2] + v.w * W[(k + 3) * 2];
    float s1 = v.x * W[(k + 0) * 2 + 1] + v.y * W[(k + 1) * 2 + 1] + v.z * W[(k + 2) * 2 + 1] + v.w * W[(k + 3) * 2 + 1];
#pragma unroll
    for (int o = 16; o > 0; o >>= 1) {
        s0 += __shfl_down_sync(0xFFFFFFFFu, s0, o);
        s1 += __shfl_down_sync(0xFFFFFFFFu, s1, o);
    }
    if (lane == 0) {
        out[w * 2 + 0] = s0 + b[0];
        out[w * 2 + 1] = s1 + b[1];
    }
}

// ---------------- host orchestration -----------------------------------------
static void build_csr_and_layer1(const float* x, const int* ei, int n, int e,
                                 int* d_off, int* d_csr, float* d_w, float* d_dinv,
                                 const float* W1, const float* b1, float* d_h1,
                                 float* d_aggx, int* d_cnt, int* d_cur, int* d_bsums,
                                 cudaStream_t st) {
    const int* src = ei;
    const int* dst = ei + e;
    int nblkN  = (n + 255) / 256;
    int nblkE  = (e + 255) / 256;
    int nblkSc = (n + 1023) / 1024;

    k_zero<<<nblkN, 256, 0, st>>>(d_cnt, n);
    k_hist<<<nblkE, 256, 0, st>>>(dst, e, d_cnt);
    k_scan_reduce<<<nblkSc, 1024, 0, st>>>(d_cnt, n, d_bsums);
    k_scan_mid<<<1, 32, 0, st>>>(d_bsums, nblkSc, d_off, n);
    k_scan_write<<<nblkSc, 1024, 0, st>>>(d_cnt, n, d_bsums, d_off, d_cur, d_dinv);
    k_csr_fill<<<nblkE, 256, 0, st>>>(src, dst, e, d_cur, d_csr, d_dinv, d_w);

    // aggX = A_hat * x ; h1 = relu(aggX @ W1 + b1)
    int aggBlocks = (n + 7) / 8;                 // 8 warps / block
    k_agg_full<<<aggBlocks, 256, 0, st>>>((const float4*)x, d_off, d_csr, d_w, d_dinv,
                                          (float4*)d_aggx, n);
    sgemm128<<<(n + 127) / 128, 256, 0, st>>>(d_aggx, W1, b1, d_h1, n, HFEAT, HFEAT, 1);
}

extern "C" void kernel_launch(void* const* d_in, const int* in_sizes, int n_in,
                              void* d_out, int out_size) {
    const float* x_l   = (const float*)d_in[0];
    const int*   ei_l  = (const int*)  d_in[1];
    const float* x_r   = (const float*)d_in[2];
    const int*   ei_r  = (const int*)  d_in[3];
    const int*   labels= (const int*)  d_in[4];
    const float* W1_l = (const float*)d_in[5];  const float* b1_l = (const float*)d_in[6];
    const float* W2_l = (const float*)d_in[7];  const float* b2_l = (const float*)d_in[8];
    const float* W1_r = (const float*)d_in[9];  const float* b1_r = (const float*)d_in[10];
    const float* W2_r = (const float*)d_in[11]; const float* b2_r = (const float*)d_in[12];
    const float* Wfc1 = (const float*)d_in[13]; const float* bfc1 = (const float*)d_in[14];
    const float* Wfc2 = (const float*)d_in[15]; const float* bfc2 = (const float*)d_in[16];
    float* out = (float*)d_out;

    int n = in_sizes[0] / HFEAT;     // 50000
    int e = in_sizes[1] / 2;         // 600000
    int p = in_sizes[4] / 3;         // 4096

    cudaStream_t st = 0;

    // resolve device-global scratch addresses (host-side symbol lookup; no alloc)
    int   *d_cnt, *d_cur, *d_bsums, *d_off_l, *d_off_r, *d_csr_l, *d_csr_r;
    float *d_w_l, *d_w_r, *d_dinv_l, *d_dinv_r, *d_aggx, *d_h1_l, *d_h1_r;
    float *d_agg2_l, *d_agg2_r, *d_merged, *d_fc1;
    cudaGetSymbolAddress((void**)&d_cnt,    g_cnt);
    cudaGetSymbolAddress((void**)&d_cur,    g_cur);
    cudaGetSymbolAddress((void**)&d_bsums,  g_bsums);
    cudaGetSymbolAddress((void**)&d_off_l,  g_off_l);
    cudaGetSymbolAddress((void**)&d_off_r,  g_off_r);
    cudaGetSymbolAddress((void**)&d_csr_l,  g_csr_l);
    cudaGetSymbolAddress((void**)&d_csr_r,  g_csr_r);
    cudaGetSymbolAddress((void**)&d_w_l,    g_w_l);
    cudaGetSymbolAddress((void**)&d_w_r,    g_w_r);
    cudaGetSymbolAddress((void**)&d_dinv_l, g_dinv_l);
    cudaGetSymbolAddress((void**)&d_dinv_r, g_dinv_r);
    cudaGetSymbolAddress((void**)&d_aggx,   g_aggx);
    cudaGetSymbolAddress((void**)&d_h1_l,   g_h1_l);
    cudaGetSymbolAddress((void**)&d_h1_r,   g_h1_r);
    cudaGetSymbolAddress((void**)&d_agg2_l, g_agg2_l);
    cudaGetSymbolAddress((void**)&d_agg2_r, g_agg2_r);
    cudaGetSymbolAddress((void**)&d_merged, g_merged);
    cudaGetSymbolAddress((void**)&d_fc1,    g_fc1);

    // ---- layer 1, both branches (full graph) ----
    build_csr_and_layer1(x_l, ei_l, n, e, d_off_l, d_csr_l, d_w_l, d_dinv_l,
                         W1_l, b1_l, d_h1_l, d_aggx, d_cnt, d_cur, d_bsums, st);
    build_csr_and_layer1(x_r, ei_r, n, e, d_off_r, d_csr_r, d_w_r, d_dinv_r,
                         W1_r, b1_r, d_h1_r, d_aggx, d_cnt, d_cur, d_bsums, st);

    // ---- layer 2: only the P selected rows per side ----
    int selBlocks = (p + 7) / 8;
    k_agg_sel<<<selBlocks, 256, 0, st>>>((const float4*)d_h1_l, d_off_l, d_csr_l, d_w_l,
                                         d_dinv_l, labels, 0, (float4*)d_agg2_l, p);
    k_agg_sel<<<selBlocks, 256, 0, st>>>((const float4*)d_h1_r, d_off_r, d_csr_r, d_w_r,
                                         d_dinv_r, labels, 1, (float4*)d_agg2_r, p);

    // layer-2 GEMMs write directly into the concatenated [P, 256] buffer
    sgemm128<<<(p + 127) / 128, 256, 0, st>>>(d_agg2_l, W2_l, b2_l, d_merged,       p, HFEAT, 2 * HFEAT, 0);
    sgemm128<<<(p + 127) / 128, 256, 0, st>>>(d_agg2_r, W2_r, b2_r, d_merged + 128, p, HFEAT, 2 * HFEAT, 0);

    // fc1: [P,256] @ [256,128] + bias, relu
    sgemm128<<<(p + 127) / 128, 256, 0, st>>>(d_merged, Wfc1, bfc1, d_fc1, p, 2 * HFEAT, HFEAT, 1);

    // fc2: [P,128] @ [128,2] + bias
    k_fc2<<<(p + 7) / 8, 256, 0, st>>>((const float4*)d_fc1, Wfc2, bfc2, out, p);
}

// round 7
// speedup vs baseline: 1.6979x; 1.6979x over previous
#include <cuda_runtime.h>
#include <cuda_bf16.h>
#include <stdint.h>

// Problem constants (GCNPair): N=50000 nodes, E=600000 edges, D=H=128, O=2, P=4096
#define NNODES 50000
#define NEDGES 600000
#define HFEAT  128
#define NPAIR  4096

// ---------------- scratch (device globals; no runtime allocation) ------------
__device__ int   g_cnt[NNODES];
__device__ int   g_bsums[128];
__device__ int   g_off_l[NNODES + 1];
__device__ int   g_off_r[NNODES + 1];
__device__ int   g_cur[NNODES];
__device__ int   g_csr_l[NEDGES];
__device__ int   g_csr_r[NEDGES];
__device__ float g_w_l  [NEDGES];           // precomputed edge weights dinv[d]*dinv[s]
__device__ float g_w_r  [NEDGES];
__device__ float g_dinv_l[NNODES];
__device__ float g_dinv_r[NNODES];
__device__ float g_aggx [NNODES * HFEAT];   // temp: (A_hat X) per branch, reused
__device__ float g_h1_l [NNODES * HFEAT];   // layer-1 output, left
__device__ float g_h1_r [NNODES * HFEAT];   // layer-1 output, right
__device__ float g_agg2_l[NPAIR * HFEAT];
__device__ float g_agg2_r[NPAIR * HFEAT];
__device__ float g_merged[NPAIR * 2 * HFEAT];
__device__ float g_fc1  [NPAIR * HFEAT];

// ---------------- CSR build ----------------
__global__ void k_zero(int* p, int n) {
    int i = blockIdx.x * blockDim.x + threadIdx.x;
    if (i < n) p[i] = 0;
}

__global__ void k_hist(const int* __restrict__ dst, int e, int* __restrict__ cnt) {
    int i = blockIdx.x * blockDim.x + threadIdx.x;
    if (i < e) atomicAdd(&cnt[dst[i]], 1);
}

// 3-phase exclusive scan of cnt[] -> offsets[]; also seeds cursor[] and dinv[]
__global__ void k_scan_reduce(const int* __restrict__ cnt, int n, int* __restrict__ bsums) {
    __shared__ int sh[1024];
    int i = blockIdx.x * 1024 + threadIdx.x;
    sh[threadIdx.x] = (i < n) ? cnt[i] : 0;
    __syncthreads();
    for (int s = 512; s > 0; s >>= 1) {
        if (threadIdx.x < s) sh[threadIdx.x] += sh[threadIdx.x + s];
        __syncthreads();
    }
    if (threadIdx.x == 0) bsums[blockIdx.x] = sh[0];
}

// parallel scan of the (<=64) block sums; was a 5.8us serial 1-thread loop
__global__ void k_scan_mid(int* bsums, int nblk, int* offsets, int n) {
    __shared__ int sh[64];
    int t = threadIdx.x;
    int v = (t < nblk) ? bsums[t] : 0;
    sh[t] = v;
    __syncthreads();
    for (int s = 1; s < 64; s <<= 1) {
        int u = (t >= s) ? sh[t - s] : 0;
        __syncthreads();
        sh[t] += u;
        __syncthreads();
    }
    if (t < nblk) bsums[t] = sh[t] - v;      // exclusive prefix
    if (t == 0) offsets[n] = sh[63];         // total
}

__global__ void k_scan_write(const int* __restrict__ cnt, int n,
                             const int* __restrict__ boffs,
                             int* __restrict__ offsets, int* __restrict__ cursor,
                             float* __restrict__ dinv) {
    __shared__ int sh[1024];
    int i = blockIdx.x * 1024 + threadIdx.x;
    int v = (i < n) ? cnt[i] : 0;
    sh[threadIdx.x] = v;
    __syncthreads();
    for (int s = 1; s < 1024; s <<= 1) {
        int t = 0;
        if (threadIdx.x >= (unsigned)s) t = sh[threadIdx.x - s];
        __syncthreads();
        if (threadIdx.x >= (unsigned)s) sh[threadIdx.x] += t;
        __syncthreads();
    }
    if (i < n) {
        int excl = sh[threadIdx.x] - v + boffs[blockIdx.x];
        offsets[i] = excl;
        cursor[i]  = excl;
        dinv[i]    = rsqrtf((float)(v + 1));   // +1 self-loop; deg > 0 always
    }
}

// Fill CSR and precompute per-edge weight dinv[dst]*dinv[src] so the hot
// aggregation loop has NO random scalar gathers (only the row gather).
__global__ void k_csr_fill(const int* __restrict__ src, const int* __restrict__ dst, int e,
                           int* __restrict__ cursor, int* __restrict__ csr_src,
                           const float* __restrict__ dinv, float* __restrict__ csr_w) {
    int i = blockIdx.x * blockDim.x + threadIdx.x;
    if (i < e) {
        int d = dst[i];
        int s = src[i];
        int pos = atomicAdd(&cursor[d], 1);
        csr_src[pos] = s;
        csr_w[pos]   = dinv[d] * dinv[s];
    }
}

// ---------------- aggregation: one warp per dst row, lane = float4 chunk ------
__device__ __forceinline__ void fma4(float4& acc, float w, const float4& u) {
    acc.x += w * u.x; acc.y += w * u.y; acc.z += w * u.z; acc.w += w * u.w;
}

__device__ __forceinline__ float4 agg_row(const float4* __restrict__ x,
                                          const int* __restrict__ csr,
                                          const float* __restrict__ csr_w,
                                          const float* __restrict__ dinv,
                                          int node, int lane, int e0, int e1) {
    float di = dinv[node];
    float4 v = x[(size_t)node * 32 + lane];
    float s = di * di;                         // self-loop weight
    float4 acc = make_float4(v.x * s, v.y * s, v.z * s, v.w * s);
    int e = e0;
    for (; e + 8 <= e1; e += 8) {
        int   si[8];
        float wi[8];
#pragma unroll
        for (int j = 0; j < 8; j++) { si[j] = csr[e + j]; wi[j] = csr_w[e + j]; }
        float4 u[8];
#pragma unroll
        for (int j = 0; j < 8; j++) u[j] = x[(size_t)si[j] * 32 + lane];
#pragma unroll
        for (int j = 0; j < 8; j++) fma4(acc, wi[j], u[j]);
    }
    for (; e + 4 <= e1; e += 4) {
        int s0 = csr[e], s1 = csr[e + 1], s2 = csr[e + 2], s3 = csr[e + 3];
        float w0 = csr_w[e],     w1 = csr_w[e + 1];
        float w2 = csr_w[e + 2], w3 = csr_w[e + 3];
        float4 u0 = x[(size_t)s0 * 32 + lane];
        float4 u1 = x[(size_t)s1 * 32 + lane];
        float4 u2 = x[(size_t)s2 * 32 + lane];
        float4 u3 = x[(size_t)s3 * 32 + lane];
        fma4(acc, w0, u0); fma4(acc, w1, u1);
        fma4(acc, w2, u2); fma4(acc, w3, u3);
    }
    for (; e < e1; e++) {
        fma4(acc, csr_w[e], x[(size_t)csr[e] * 32 + lane]);
    }
    return acc;
}

__global__ void k_agg_full(const float4* __restrict__ x,
                           const int* __restrict__ off, const int* __restrict__ csr,
                           const float* __restrict__ csr_w,
                           const float* __restrict__ dinv,
                           float4* __restrict__ out, int n) {
    int w = (blockIdx.x * blockDim.x + threadIdx.x) >> 5;
    int lane = threadIdx.x & 31;
    if (w >= n) return;
    out[(size_t)w * 32 + lane] = agg_row(x, csr, csr_w, dinv, w, lane, off[w], off[w + 1]);
}

// selective aggregation: rows are labels[p*3+col]; only P rows computed
__global__ void k_agg_sel(const float4* __restrict__ h,
                          const int* __restrict__ off, const int* __restrict__ csr,
                          const float* __restrict__ csr_w,
                          const float* __restrict__ dinv,
                          const int* __restrict__ labels, int col,
                          float4* __restrict__ out, int p) {
    int w = (blockIdx.x * blockDim.x + threadIdx.x) >> 5;
    int lane = threadIdx.x & 31;
    if (w >= p) return;
    int node = labels[w * 3 + col];
    out[(size_t)w * 32 + lane] = agg_row(h, csr, csr_w, dinv, node, lane, off[node], off[node + 1]);
}

// ---------------- TF32 tensor-core GEMM --------------------------------------
// C[M x 128] = A[M x K] * B[K x 128] (+bias, opt relu).  K % 16 == 0.
// Block tile 128x128, 8 warps (4x2), warp tile 32x64 via m16n8k8 tf32 mma.
__device__ __forceinline__ uint32_t f2tf32(float f) {
    uint32_t r;
    asm("cvt.rna.tf32.f32 %0, %1;" : "=r"(r) : "f"(f));
    return r;
}

__device__ __forceinline__ void mma_tf32(float* d, const uint32_t* a,
                                         const uint32_t* b, const float* c) {
    asm volatile(
        "mma.sync.aligned.m16n8k8.row.col.f32.tf32.tf32.f32 "
        "{%0,%1,%2,%3}, {%4,%5,%6,%7}, {%8,%9}, {%10,%11,%12,%13};\n"
        : "=f"(d[0]), "=f"(d[1]), "=f"(d[2]), "=f"(d[3])
        : "r"(a[0]), "r"(a[1]), "r"(a[2]), "r"(a[3]),
          "r"(b[0]), "r"(b[1]),
          "f"(c[0]), "f"(c[1]), "f"(c[2]), "f"(c[3]));
}

#define TG_STRIDE 136   // 136 mod 32 = 8 -> conflict-free fragment loads

__global__ __launch_bounds__(256)
void tgemm128(const float* __restrict__ A, const float* __restrict__ B,
              const float* __restrict__ bias, float* __restrict__ C,
              int M, int K, int ldc, int relu) {
    __shared__ uint32_t As[16][TG_STRIDE];   // [k][row], tf32 bits
    __shared__ uint32_t Bs[16][TG_STRIDE];   // [k][col], tf32 bits
    int tid  = threadIdx.x;
    int lane = tid & 31, wid = tid >> 5;
    int wm = wid >> 1, wn = wid & 1;         // warp grid 4 x 2
    int g = lane >> 2, tig = lane & 3;
    int blockRow = blockIdx.x * 128;

    float acc[2][8][4];
#pragma unroll
    for (int mt = 0; mt < 2; mt++)
#pragma unroll
        for (int nt = 0; nt < 8; nt++)
#pragma unroll
            for (int j = 0; j < 4; j++) acc[mt][nt][j] = 0.f;

    int aRow = tid >> 1;             // 0..127
    int aK   = (tid & 1) * 8;        // 0 or 8
    int bK   = tid >> 4;             // 0..15
    int bC   = (tid & 15) * 8;       // 0..120

    for (int k0 = 0; k0 < K; k0 += 16) {
        // stage A: row aRow, cols [k0+aK, k0+aK+8), transposed into As[k][row]
        int gr = blockRow + aRow;
        float4 av0, av1;
        if (gr < M) {
            av0 = *(const float4*)(A + (size_t)gr * K + k0 + aK);
            av1 = *(const float4*)(A + (size_t)gr * K + k0 + aK + 4);
        } else {
            av0 = make_float4(0.f, 0.f, 0.f, 0.f);
            av1 = av0;
        }
        As[aK + 0][aRow] = f2tf32(av0.x);
        As[aK + 1][aRow] = f2tf32(av0.y);
        As[aK + 2][aRow] = f2tf32(av0.z);
        As[aK + 3][aRow] = f2tf32(av0.w);
        As[aK + 4][aRow] = f2tf32(av1.x);
        As[aK + 5][aRow] = f2tf32(av1.y);
        As[aK + 6][aRow] = f2tf32(av1.z);
        As[aK + 7][aRow] = f2tf32(av1.w);
        // stage B: row k0+bK, cols [bC, bC+8)
        const float4* bp = (const float4*)(B + (size_t)(k0 + bK) * 128 + bC);
        float4 bv0 = bp[0], bv1 = bp[1];
        Bs[bK][bC + 0] = f2tf32(bv0.x);
        Bs[bK][bC + 1] = f2tf32(bv0.y);
        Bs[bK][bC + 2] = f2tf32(bv0.z);
        Bs[bK][bC + 3] = f2tf32(bv0.w);
        Bs[bK][bC + 4] = f2tf32(bv1.x);
        Bs[bK][bC + 5] = f2tf32(bv1.y);
        Bs[bK][bC + 6] = f2tf32(bv1.z);
        Bs[bK][bC + 7] = f2tf32(bv1.w);
        __syncthreads();

#pragma unroll
        for (int kk = 0; kk < 16; kk += 8) {
            uint32_t af[2][4];
#pragma unroll
            for (int mt = 0; mt < 2; mt++) {
                int r = wm * 32 + mt * 16 + g;
                af[mt][0] = As[kk + tig][r];
                af[mt][1] = As[kk + tig][r + 8];
                af[mt][2] = As[kk + tig + 4][r];
                af[mt][3] = As[kk + tig + 4][r + 8];
            }
            uint32_t bf[8][2];
#pragma unroll
            for (int nt = 0; nt < 8; nt++) {
                int c = wn * 64 + nt * 8 + g;
                bf[nt][0] = Bs[kk + tig][c];
                bf[nt][1] = Bs[kk + tig + 4][c];
            }
#pragma unroll
            for (int mt = 0; mt < 2; mt++)
#pragma unroll
                for (int nt = 0; nt < 8; nt++)
                    mma_tf32(acc[mt][nt], af[mt], bf[nt], acc[mt][nt]);
        }
        __syncthreads();
    }

    // epilogue: bias (+relu), float2 stores
#pragma unroll
    for (int mt = 0; mt < 2; mt++) {
        int r = blockRow + wm * 32 + mt * 16 + g;
#pragma unroll
        for (int nt = 0; nt < 8; nt++) {
            int c = wn * 64 + nt * 8 + tig * 2;
            float bx = bias[c], by = bias[c + 1];
            float v0 = acc[mt][nt][0] + bx, v1 = acc[mt][nt][1] + by;
            float v2 = acc[mt][nt][2] + bx, v3 = acc[mt][nt][3] + by;
            if (relu) {
                v0 = fmaxf(v0, 0.f); v1 = fmaxf(v1, 0.f);
                v2 = fmaxf(v2, 0.f); v3 = fmaxf(v3, 0.f);
            }
            if (r < M)     *(float2*)(C + (size_t)r * ldc + c)       = make_float2(v0, v1);
            if (r + 8 < M) *(float2*)(C + (size_t)(r + 8) * ldc + c) = make_float2(v2, v3);
        }
    }
}

// ---------------- fc2: [P,128] x [128,2] + b, one warp per row ----------------
__global__ void k_fc2(const float4* __restrict__ h, const float* __restrict__ W,
                      const float* __restrict__ b, float* __restrict__ out, int p) {
    int w = (blockIdx.x * blockDim.x + threadIdx.x) >> 5;
    int lane = threadIdx.x & 31;
    if (w >= p) return;
    float4 v = h[(size_t)w * 32 + lane];
    int k = lane * 4;
    float s0 = v.x * W[(k + 0) * 2] + v.y * W[(k + 1) * 2] + v.z * W[(k + 2) * 2] + v.w * W[(k + 3) * 2];
    float s1 = v.x * W[(k + 0) * 2 + 1] + v.y * W[(k + 1) * 2 + 1] + v.z * W[(k + 2) * 2 + 1] + v.w * W[(k + 3) * 2 + 1];
#pragma unroll
    for (int o = 16; o > 0; o >>= 1) {
        s0 += __shfl_down_sync(0xFFFFFFFFu, s0, o);
        s1 += __shfl_down_sync(0xFFFFFFFFu, s1, o);
    }
    if (lane == 0) {
        out[w * 2 + 0] = s0 + b[0];
        out[w * 2 + 1] = s1 + b[1];
    }
}

// ---------------- host orchestration -----------------------------------------
static void build_csr_and_layer1(const float* x, const int* ei, int n, int e,
                                 int* d_off, int* d_csr, float* d_w, float* d_dinv,
                                 const float* W1, const float* b1, float* d_h1,
                                 float* d_aggx, int* d_cnt, int* d_cur, int* d_bsums,
                                 cudaStream_t st) {
    const int* src = ei;
    const int* dst = ei + e;
    int nblkN  = (n + 255) / 256;
    int nblkE  = (e + 255) / 256;
    int nblkSc = (n + 1023) / 1024;

    k_zero<<<nblkN, 256, 0, st>>>(d_cnt, n);
    k_hist<<<nblkE, 256, 0, st>>>(dst, e, d_cnt);
    k_scan_reduce<<<nblkSc, 1024, 0, st>>>(d_cnt, n, d_bsums);
    k_scan_mid<<<1, 64, 0, st>>>(d_bsums, nblkSc, d_off, n);
    k_scan_write<<<nblkSc, 1024, 0, st>>>(d_cnt, n, d_bsums, d_off, d_cur, d_dinv);
    k_csr_fill<<<nblkE, 256, 0, st>>>(src, dst, e, d_cur, d_csr, d_dinv, d_w);

    // aggX = A_hat * x ; h1 = relu(aggX @ W1 + b1)
    int aggBlocks = (n + 7) / 8;                 // 8 warps / block
    k_agg_full<<<aggBlocks, 256, 0, st>>>((const float4*)x, d_off, d_csr, d_w, d_dinv,
                                          (float4*)d_aggx, n);
    tgemm128<<<(n + 127) / 128, 256, 0, st>>>(d_aggx, W1, b1, d_h1, n, HFEAT, HFEAT, 1);
}

extern "C" void kernel_launch(void* const* d_in, const int* in_sizes, int n_in,
                              void* d_out, int out_size) {
    const float* x_l   = (const float*)d_in[0];
    const int*   ei_l  = (const int*)  d_in[1];
    const float* x_r   = (const float*)d_in[2];
    const int*   ei_r  = (const int*)  d_in[3];
    const int*   labels= (const int*)  d_in[4];
    const float* W1_l = (const float*)d_in[5];  const float* b1_l = (const float*)d_in[6];
    const float* W2_l = (const float*)d_in[7];  const float* b2_l = (const float*)d_in[8];
    const float* W1_r = (const float*)d_in[9];  const float* b1_r = (const float*)d_in[10];
    const float* W2_r = (const float*)d_in[11]; const float* b2_r = (const float*)d_in[12];
    const float* Wfc1 = (const float*)d_in[13]; const float* bfc1 = (const float*)d_in[14];
    const float* Wfc2 = (const float*)d_in[15]; const float* bfc2 = (const float*)d_in[16];
    float* out = (float*)d_out;

    int n = in_sizes[0] / HFEAT;     // 50000
    int e = in_sizes[1] / 2;         // 600000
    int p = in_sizes[4] / 3;         // 4096

    cudaStream_t st = 0;

    // resolve device-global scratch addresses (host-side symbol lookup; no alloc)
    int   *d_cnt, *d_cur, *d_bsums, *d_off_l, *d_off_r, *d_csr_l, *d_csr_r;
    float *d_w_l, *d_w_r, *d_dinv_l, *d_dinv_r, *d_aggx, *d_h1_l, *d_h1_r;
    float *d_agg2_l, *d_agg2_r, *d_merged, *d_fc1;
    cudaGetSymbolAddress((void**)&d_cnt,    g_cnt);
    cudaGetSymbolAddress((void**)&d_cur,    g_cur);
    cudaGetSymbolAddress((void**)&d_bsums,  g_bsums);
    cudaGetSymbolAddress((void**)&d_off_l,  g_off_l);
    cudaGetSymbolAddress((void**)&d_off_r,  g_off_r);
    cudaGetSymbolAddress((void**)&d_csr_l,  g_csr_l);
    cudaGetSymbolAddress((void**)&d_csr_r,  g_csr_r);
    cudaGetSymbolAddress((void**)&d_w_l,    g_w_l);
    cudaGetSymbolAddress((void**)&d_w_r,    g_w_r);
    cudaGetSymbolAddress((void**)&d_dinv_l, g_dinv_l);
    cudaGetSymbolAddress((void**)&d_dinv_r, g_dinv_r);
    cudaGetSymbolAddress((void**)&d_aggx,   g_aggx);
    cudaGetSymbolAddress((void**)&d_h1_l,   g_h1_l);
    cudaGetSymbolAddress((void**)&d_h1_r,   g_h1_r);
    cudaGetSymbolAddress((void**)&d_agg2_l, g_agg2_l);
    cudaGetSymbolAddress((void**)&d_agg2_r, g_agg2_r);
    cudaGetSymbolAddress((void**)&d_merged, g_merged);
    cudaGetSymbolAddress((void**)&d_fc1,    g_fc1);

    // ---- layer 1, both branches (full graph) ----
    build_csr_and_layer1(x_l, ei_l, n, e, d_off_l, d_csr_l, d_w_l, d_dinv_l,
                         W1_l, b1_l, d_h1_l, d_aggx, d_cnt, d_cur, d_bsums, st);
    build_csr_and_layer1(x_r, ei_r, n, e, d_off_r, d_csr_r, d_w_r, d_dinv_r,
                         W1_r, b1_r, d_h1_r, d_aggx, d_cnt, d_cur, d_bsums, st);

    // ---- layer 2: only the P selected rows per side ----
    int selBlocks = (p + 7) / 8;
    k_agg_sel<<<selBlocks, 256, 0, st>>>((const float4*)d_h1_l, d_off_l, d_csr_l, d_w_l,
                                         d_dinv_l, labels, 0, (float4*)d_agg2_l, p);
    k_agg_sel<<<selBlocks, 256, 0, st>>>((const float4*)d_h1_r, d_off_r, d_csr_r, d_w_r,
                                         d_dinv_r, labels, 1, (float4*)d_agg2_r, p);

    // layer-2 GEMMs write directly into the concatenated [P, 256] buffer
    tgemm128<<<(p + 127) / 128, 256, 0, st>>>(d_agg2_l, W2_l, b2_l, d_merged,       p, HFEAT, 2 * HFEAT, 0);
    tgemm128<<<(p + 127) / 128, 256, 0, st>>>(d_agg2_r, W2_r, b2_r, d_merged + 128, p, HFEAT, 2 * HFEAT, 0);

    // fc1: [P,256] @ [256,128] + bias, relu
    tgemm128<<<(p + 127) / 128, 256, 0, st>>>(d_merged, Wfc1, bfc1, d_fc1, p, 2 * HFEAT, HFEAT, 1);

    // fc2: [P,128] @ [128,2] + bias
    k_fc2<<<(p + 7) / 8, 256, 0, st>>>((const float4*)d_fc1, Wfc2, bfc2, out, p);
}